// round 1
// baseline (speedup 1.0000x reference)
#include <cuda_runtime.h>
#include <cstdint>

static constexpr int NE_MAX = 32768;
static constexpr int KC = 19;
static constexpr int CH = 128;

// scratch for radial MLP output [N, 1536] (device global: no allocations allowed)
__device__ float g_rad[(size_t)NE_MAX * 1536];

// ---------------------------------------------------------------------------
// Shared micro-kernel helpers: 64 edges x 128 cols tile, 256 threads,
// per-thread 4x8 accumulator. A stored k-major As[k][e] (pitch 68),
// W stored k-major Ws[k][j] (pitch 132).
// ---------------------------------------------------------------------------

__device__ __forceinline__ void zero_acc(float acc[4][8]) {
#pragma unroll
  for (int ee = 0; ee < 4; ++ee)
#pragma unroll
    for (int jj = 0; jj < 8; ++jj) acc[ee][jj] = 0.f;
}

// GEMM over K=128 from a k-major smem A-tile; W streamed from global in
// 32-wide K chunks through WS. Ends with __syncthreads().
__device__ __forceinline__ void rad_gemm128(const float* __restrict__ AT,
                                            const float* __restrict__ Wg,
                                            float* __restrict__ WS,
                                            float acc[4][8],
                                            int ty, int tx, int t)
{
  const int jL  = t >> 1;
  const int kk0 = (t & 1) * 16;
  const float* wrow = Wg + jL * 128 + kk0;
#pragma unroll 1
  for (int kc = 0; kc < 4; ++kc) {
#pragma unroll
    for (int u = 0; u < 4; ++u) {
      float4 v = *(const float4*)(wrow + kc * 32 + u * 4);
      const int kk = kk0 + u * 4;
      WS[(kk + 0) * 132 + jL] = v.x;
      WS[(kk + 1) * 132 + jL] = v.y;
      WS[(kk + 2) * 132 + jL] = v.z;
      WS[(kk + 3) * 132 + jL] = v.w;
    }
    __syncthreads();
#pragma unroll
    for (int kk = 0; kk < 32; ++kk) {
      float4 a  = *(const float4*)(AT + (kc * 32 + kk) * 68 + ty * 4);
      float4 b0 = *(const float4*)(WS + kk * 132 + tx * 8);
      float4 b1 = *(const float4*)(WS + kk * 132 + tx * 8 + 4);
      float av[4] = {a.x, a.y, a.z, a.w};
      float bv[8] = {b0.x, b0.y, b0.z, b0.w, b1.x, b1.y, b1.z, b1.w};
#pragma unroll
      for (int ee = 0; ee < 4; ++ee)
#pragma unroll
        for (int jj = 0; jj < 8; ++jj)
          acc[ee][jj] = fmaf(av[ee], bv[jj], acc[ee][jj]);
    }
    __syncthreads();
  }
}

// store accumulator transposed (j-major, k-major for next layer) with bias add
__device__ __forceinline__ void store_bias_T(float* __restrict__ OT,
                                             const float acc[4][8],
                                             const float* __restrict__ bias,
                                             int ty, int tx)
{
  float4 q0 = *(const float4*)(bias + tx * 8);
  float4 q1 = *(const float4*)(bias + tx * 8 + 4);
  float bb[8] = {q0.x, q0.y, q0.z, q0.w, q1.x, q1.y, q1.z, q1.w};
#pragma unroll
  for (int jj = 0; jj < 8; ++jj) {
    const int j = tx * 8 + jj;
#pragma unroll
    for (int ee = 0; ee < 4; ++ee)
      OT[j * 68 + ty * 4 + ee] = acc[ee][jj] + bb[jj];
  }
}

// LayerNorm over j (128) + SiLU, in place on a k-major [128][68] tile.
// 4 threads per edge, shfl-combined.
__device__ __forceinline__ void ln_silu(float* __restrict__ HT,
                                        const float* __restrict__ g,
                                        const float* __restrict__ be,
                                        int t)
{
  const int e = t >> 2, q = t & 3;
  float vv[32];
  float s = 0.f, s2 = 0.f;
#pragma unroll
  for (int u = 0; u < 32; ++u) {
    float v = HT[(q * 32 + u) * 68 + e];
    vv[u] = v;
    s += v;
    s2 += v * v;
  }
  s  += __shfl_xor_sync(0xffffffffu, s, 1);
  s2 += __shfl_xor_sync(0xffffffffu, s2, 1);
  s  += __shfl_xor_sync(0xffffffffu, s, 2);
  s2 += __shfl_xor_sync(0xffffffffu, s2, 2);
  const float mu  = s * (1.0f / 128.0f);
  const float var = fmaf(-mu, mu, s2 * (1.0f / 128.0f));
  const float rin = rsqrtf(var + 1e-5f);
#pragma unroll
  for (int u = 0; u < 32; ++u) {
    const int j = q * 32 + u;
    float v = (vv[u] - mu) * rin * g[j] + be[j];
    v = v / (1.0f + expf(-v));   // SiLU
    HT[j * 68 + e] = v;
  }
}

// ---------------------------------------------------------------------------
// Radial MLP: per 64-edge tile, fused LN+SiLU MLP 128->128->128->1536
// dynamic smem: HA[128][68] + HB[128][68] + WS[32][132] = 86528 B
// ---------------------------------------------------------------------------
__global__ __launch_bounds__(256)
void radial_kernel(const float* __restrict__ xe,
                   const float* __restrict__ w1, const float* __restrict__ b1,
                   const float* __restrict__ g1, const float* __restrict__ be1,
                   const float* __restrict__ w2, const float* __restrict__ b2,
                   const float* __restrict__ g2, const float* __restrict__ be2,
                   const float* __restrict__ w3, const float* __restrict__ b3)
{
  extern __shared__ float smx[];
  float* HA = smx;                 // [128][68]
  float* HB = smx + 128 * 68;      // [128][68]
  float* WS = smx + 2 * 128 * 68;  // [32][132]
  const int t  = threadIdx.x;
  const int ty = t >> 4, tx = t & 15;
  const size_t e0 = (size_t)blockIdx.x * 64;

  // load x_edge tile transposed -> HA[k][e]
  {
    const int e = t >> 2, q = t & 3;
    const float* src = xe + (e0 + e) * 128 + q * 32;
#pragma unroll
    for (int u = 0; u < 8; ++u) {
      float4 v = *(const float4*)(src + u * 4);
      const int k = q * 32 + u * 4;
      HA[(k + 0) * 68 + e] = v.x;
      HA[(k + 1) * 68 + e] = v.y;
      HA[(k + 2) * 68 + e] = v.z;
      HA[(k + 3) * 68 + e] = v.w;
    }
  }
  __syncthreads();

  float acc[4][8];

  // layer 1: HA -> HB
  zero_acc(acc);
  rad_gemm128(HA, w1, WS, acc, ty, tx, t);
  store_bias_T(HB, acc, b1, ty, tx);
  __syncthreads();
  ln_silu(HB, g1, be1, t);
  __syncthreads();

  // layer 2: HB -> HA
  zero_acc(acc);
  rad_gemm128(HB, w2, WS, acc, ty, tx, t);
  store_bias_T(HA, acc, b2, ty, tx);
  __syncthreads();
  ln_silu(HA, g2, be2, t);
  __syncthreads();

  // layer 3: HA -> g_rad (12 chunks of 128 output channels)
#pragma unroll 1
  for (int jc = 0; jc < 12; ++jc) {
    zero_acc(acc);
    rad_gemm128(HA, w3 + (size_t)jc * 128 * 128, WS, acc, ty, tx, t);
    float4 q0 = *(const float4*)(b3 + jc * 128 + tx * 8);
    float4 q1 = *(const float4*)(b3 + jc * 128 + tx * 8 + 4);
    float bb[8] = {q0.x, q0.y, q0.z, q0.w, q1.x, q1.y, q1.z, q1.w};
#pragma unroll
    for (int ee = 0; ee < 4; ++ee) {
      const size_t e = e0 + ty * 4 + ee;
      float* dst = g_rad + e * 1536 + jc * 128 + tx * 8;
      float4 o0, o1;
      o0.x = acc[ee][0] + bb[0]; o0.y = acc[ee][1] + bb[1];
      o0.z = acc[ee][2] + bb[2]; o0.w = acc[ee][3] + bb[3];
      o1.x = acc[ee][4] + bb[4]; o1.y = acc[ee][5] + bb[5];
      o1.z = acc[ee][6] + bb[6]; o1.w = acc[ee][7] + bb[7];
      *(float4*)dst       = o0;
      *(float4*)(dst + 4) = o1;
    }
  }
}

// ---------------------------------------------------------------------------
// Main SO2 GEMM: Y[n, rows[jb], :] = sum_k A[n,k] * W[jb*128+mo, k]  (+bias)
//   A[n, i*128+c] = x[n, rows[i], c] * rad[n, radoff + i*128 + c]
// Block tile: 64 edges x 128 out channels, K chunked by 32.
// rows packed 5 bits each into rowsPacked (values 0..18).
// ---------------------------------------------------------------------------
template <int SZ, bool BIAS>
__global__ __launch_bounds__(256)
void so2_gemm_kernel(const float* __restrict__ x,
                     const float* __restrict__ W,
                     const float* __restrict__ bias,
                     float* __restrict__ out,
                     unsigned rowsPacked, int radoff)
{
  __shared__ __align__(16) float As[32 * 68];
  __shared__ __align__(16) float Ws[32 * 132];
  constexpr int Kdim = SZ * 128;
  const int t  = threadIdx.x;
  const int ty = t >> 4, tx = t & 15;
  const size_t e0 = (size_t)blockIdx.x * 64;
  const int jb = blockIdx.y;

  const int eL   = t >> 2;
  const int kk0a = (t & 3) * 8;
  const int jL   = t >> 1;
  const int kk0w = (t & 1) * 16;

  const float* wrow = W + (size_t)(jb * 128 + jL) * Kdim + kk0w;
  const float* rrow = g_rad + (e0 + eL) * 1536 + radoff + kk0a;
  const float* xrow = x + (e0 + eL) * (size_t)(KC * CH) + kk0a;

  float acc[4][8];
  zero_acc(acc);

#pragma unroll 1
  for (int kc = 0; kc < Kdim / 32; ++kc) {
    const int i  = kc >> 2;            // coefficient index within set
    const int c0 = (kc & 3) * 32;      // channel base within coefficient
    const int row = (rowsPacked >> (5 * i)) & 31;
    const float* xs = xrow + row * 128 + c0;
    const float* rs = rrow + kc * 32;
#pragma unroll
    for (int u = 0; u < 2; ++u) {
      float4 vx = *(const float4*)(xs + u * 4);
      float4 vr = *(const float4*)(rs + u * 4);
      const int kk = kk0a + u * 4;
      As[(kk + 0) * 68 + eL] = vx.x * vr.x;
      As[(kk + 1) * 68 + eL] = vx.y * vr.y;
      As[(kk + 2) * 68 + eL] = vx.z * vr.z;
      As[(kk + 3) * 68 + eL] = vx.w * vr.w;
    }
#pragma unroll
    for (int u = 0; u < 4; ++u) {
      float4 v = *(const float4*)(wrow + kc * 32 + u * 4);
      const int kk = kk0w + u * 4;
      Ws[(kk + 0) * 132 + jL] = v.x;
      Ws[(kk + 1) * 132 + jL] = v.y;
      Ws[(kk + 2) * 132 + jL] = v.z;
      Ws[(kk + 3) * 132 + jL] = v.w;
    }
    __syncthreads();
#pragma unroll
    for (int kk = 0; kk < 32; ++kk) {
      float4 a  = *(const float4*)(As + kk * 68 + ty * 4);
      float4 b0 = *(const float4*)(Ws + kk * 132 + tx * 8);
      float4 b1 = *(const float4*)(Ws + kk * 132 + tx * 8 + 4);
      float av[4] = {a.x, a.y, a.z, a.w};
      float bv[8] = {b0.x, b0.y, b0.z, b0.w, b1.x, b1.y, b1.z, b1.w};
#pragma unroll
      for (int ee = 0; ee < 4; ++ee)
#pragma unroll
        for (int jj = 0; jj < 8; ++jj)
          acc[ee][jj] = fmaf(av[ee], bv[jj], acc[ee][jj]);
    }
    __syncthreads();
  }

  float bb[8];
  if (BIAS) {
    float4 q0 = *(const float4*)(bias + jb * 128 + tx * 8);
    float4 q1 = *(const float4*)(bias + jb * 128 + tx * 8 + 4);
    bb[0] = q0.x; bb[1] = q0.y; bb[2] = q0.z; bb[3] = q0.w;
    bb[4] = q1.x; bb[5] = q1.y; bb[6] = q1.z; bb[7] = q1.w;
  } else {
#pragma unroll
    for (int jj = 0; jj < 8; ++jj) bb[jj] = 0.f;
  }

  const int orow = (rowsPacked >> (5 * jb)) & 31;
#pragma unroll
  for (int ee = 0; ee < 4; ++ee) {
    const size_t e = e0 + ty * 4 + ee;
    float* dst = out + (e * KC + orow) * CH + tx * 8;
    float4 o0, o1;
    o0.x = acc[ee][0] + bb[0]; o0.y = acc[ee][1] + bb[1];
    o0.z = acc[ee][2] + bb[2]; o0.w = acc[ee][3] + bb[3];
    o1.x = acc[ee][4] + bb[4]; o1.y = acc[ee][5] + bb[5];
    o1.z = acc[ee][6] + bb[6]; o1.w = acc[ee][7] + bb[7];
    *(float4*)dst       = o0;
    *(float4*)(dst + 4) = o1;
  }
}

// ---------------------------------------------------------------------------

static inline unsigned pk(int a, int b, int c, int d, int e)
{
  return (unsigned)a | ((unsigned)b << 5) | ((unsigned)c << 10) |
         ((unsigned)d << 15) | ((unsigned)e << 20);
}

extern "C" void kernel_launch(void* const* d_in, const int* in_sizes, int n_in,
                              void* d_out, int out_size)
{
  const float* x    = (const float*)d_in[0];
  const float* xe   = (const float*)d_in[1];
  const float* fc0w = (const float*)d_in[2];
  const float* fc0b = (const float*)d_in[3];
  const float* fc1w = (const float*)d_in[4];
  const float* fc2w = (const float*)d_in[5];
  const float* rw1  = (const float*)d_in[6];
  const float* rb1  = (const float*)d_in[7];
  const float* rg1  = (const float*)d_in[8];
  const float* rbe1 = (const float*)d_in[9];
  const float* rw2  = (const float*)d_in[10];
  const float* rb2  = (const float*)d_in[11];
  const float* rg2  = (const float*)d_in[12];
  const float* rbe2 = (const float*)d_in[13];
  const float* rw3  = (const float*)d_in[14];
  const float* rb3  = (const float*)d_in[15];
  float* out = (float*)d_out;

  const int N  = in_sizes[1] / CH;   // edges
  const int nb = N / 64;

  const int smem = (2 * 128 * 68 + 32 * 132) * 4;  // 86528 B
  cudaFuncSetAttribute(radial_kernel,
                       cudaFuncAttributeMaxDynamicSharedMemorySize, smem);

  radial_kernel<<<nb, 256, smem>>>(xe, rw1, rb1, rg1, rbe1,
                                   rw2, rb2, rg2, rbe2, rw3, rb3);

  // m = 0 block (bias), rows {0,2,6,11,16}, radoff 0, K=640
  so2_gemm_kernel<5, true ><<<dim3(nb, 5), 256>>>(x, fc0w, fc0b, out,
                                                  pk(0, 2, 6, 11, 16), 0);
  // m = 1, +m rows {3,7,12,17} and -m rows {1,5,10,15}, radoff 640, K=512
  so2_gemm_kernel<4, false><<<dim3(nb, 4), 256>>>(x, fc1w, nullptr, out,
                                                  pk(3, 7, 12, 17, 0), 640);
  so2_gemm_kernel<4, false><<<dim3(nb, 4), 256>>>(x, fc1w, nullptr, out,
                                                  pk(1, 5, 10, 15, 0), 640);
  // m = 2, +m rows {8,13,18} and -m rows {4,9,14}, radoff 1152, K=384
  so2_gemm_kernel<3, false><<<dim3(nb, 3), 256>>>(x, fc2w, nullptr, out,
                                                  pk(8, 13, 18, 0, 0), 1152);
  so2_gemm_kernel<3, false><<<dim3(nb, 3), 256>>>(x, fc2w, nullptr, out,
                                                  pk(4, 9, 14, 0, 0), 1152);
}

// round 3
// speedup vs baseline: 3.1392x; 3.1392x over previous
#include <cuda_runtime.h>
#include <cuda_bf16.h>
#include <cstdint>

static constexpr int NE_MAX = 32768;
static constexpr int KC = 19;
static constexpr int CH = 128;

// weight segment offsets inside g_Whi/g_Wlo (elements)
static constexpr int W_FC0 = 0;                 // 640*640
static constexpr int W_FC1 = 409600;            // 512*512
static constexpr int W_FC2 = 671744;            // 384*384
static constexpr int W_W3  = 819200;            // 1536*128
static constexpr int W_TOT = 1015808;

// ------------------------- device scratch (no allocs allowed) ---------------
__device__ float g_rad[(size_t)NE_MAX * 1536];
__device__ __align__(16) __nv_bfloat16 g_h2hi[(size_t)NE_MAX * CH];
__device__ __align__(16) __nv_bfloat16 g_h2lo[(size_t)NE_MAX * CH];
__device__ __align__(16) __nv_bfloat16 g_Whi[W_TOT];
__device__ __align__(16) __nv_bfloat16 g_Wlo[W_TOT];

// ------------------------- helpers ------------------------------------------
__device__ __forceinline__ uint32_t smem_u32(const void* p) {
  uint32_t a;
  asm("{ .reg .u64 t; cvta.to.shared.u64 t, %1; cvt.u32.u64 %0, t; }"
      : "=r"(a) : "l"(p));
  return a;
}
__device__ __forceinline__ void cp16(uint32_t dst, const void* src) {
  asm volatile("cp.async.cg.shared.global [%0], [%1], 16;" :: "r"(dst), "l"(src));
}
__device__ __forceinline__ void cp_commit() {
  asm volatile("cp.async.commit_group;");
}
__device__ __forceinline__ void cp_wait0() {
  asm volatile("cp.async.wait_group 0;" ::: "memory");
}
__device__ __forceinline__ void mma16816(float* c, const uint32_t* a,
                                         uint32_t b0, uint32_t b1) {
  asm volatile(
      "mma.sync.aligned.m16n8k16.row.col.f32.bf16.bf16.f32 "
      "{%0,%1,%2,%3}, {%4,%5,%6,%7}, {%8,%9}, {%0,%1,%2,%3};"
      : "+f"(c[0]), "+f"(c[1]), "+f"(c[2]), "+f"(c[3])
      : "r"(a[0]), "r"(a[1]), "r"(a[2]), "r"(a[3]), "r"(b0), "r"(b1));
}
__device__ __forceinline__ void split2(float v, __nv_bfloat16& h, __nv_bfloat16& l) {
  h = __float2bfloat16(v);
  l = __float2bfloat16(v - __bfloat162float(h));
}

// smem tile layout (bytes), per buffer: AH 0, AL 10240, WH 20480, WL 30720.
// Tiles are [128 rows][32 k] bf16 with row pitch 40 elems (80 B) -> 10240 B.
static constexpr int T_AL = 10240, T_WH = 20480, T_WL = 30720;
static constexpr int BUFB = 40960;       // bytes per buffer
static constexpr int SMEM_G = 2 * BUFB;  // 81920

// ============================================================================
// GEMM: D[128 edges x 128 out] = A @ W^T (+bias), 3-term bf16 split via
// mma.sync m16n8k16. ASEL=1: A[n,k] = x[n, xrow(k-blk)*128 + c] * rad[n, radoff+k]
// (fp32 gather+FiLM, split in-kernel). ASEL=0: A = h2 split (bf16 pre-stored),
// output to g_rad.
// Grid: (jb, edge_tile); 512 threads; warp tile 32x32.
// ============================================================================
template <int ASEL>
__global__ void __launch_bounds__(512)
mma_gemm(const float* __restrict__ x, unsigned rowsPacked, int radoff,
         int woff, int K, const float* __restrict__ bias,
         float* __restrict__ outp, int ostride, unsigned orowPack)
{
  extern __shared__ char sm[];
  const int t = threadIdx.x;
  const int jb = blockIdx.x;
  const size_t e0 = (size_t)blockIdx.y * 128;

  // staging thread mapping: 4 threads per row, 8 cols (16 B) each
  const int srow = t >> 2, sq = t & 3;
  const uint32_t sb = smem_u32(sm);
  const uint32_t wdH = sb + T_WH + srow * 80 + sq * 16;
  const uint32_t wdL = sb + T_WL + srow * 80 + sq * 16;
  const uint32_t adH = sb + srow * 80 + sq * 16;
  const uint32_t adL = sb + T_AL + srow * 80 + sq * 16;
  char* const aHp = sm + srow * 80 + sq * 16;
  char* const aLp = sm + T_AL + srow * 80 + sq * 16;

  const __nv_bfloat16* wh = g_Whi + woff + (size_t)(jb * 128 + srow) * K + sq * 8;
  const __nv_bfloat16* wl = g_Wlo + woff + (size_t)(jb * 128 + srow) * K + sq * 8;
  const __nv_bfloat16* h2h = g_h2hi + (e0 + srow) * 128 + sq * 8;
  const __nv_bfloat16* h2l = g_h2lo + (e0 + srow) * 128 + sq * 8;
  const float* xb = x + (e0 + srow) * (size_t)(KC * CH) + sq * 8;
  const float* rb = g_rad + (e0 + srow) * 1536 + radoff + sq * 8;

  const int nch = K >> 5;

  // compute-side mapping
  const int wid = t >> 5, lane = t & 31;
  const int wr = wid & 3, wc = wid >> 2;
  const int gq = lane >> 2, tg = lane & 3;
  const int aoff = (wr * 32 + gq) * 80 + tg * 4;
  const int boff = T_WH + (wc * 32 + gq) * 80 + tg * 4;

  float acc[2][4][4];
#pragma unroll
  for (int m = 0; m < 2; ++m)
#pragma unroll
    for (int n = 0; n < 4; ++n)
#pragma unroll
      for (int u = 0; u < 4; ++u) acc[m][n][u] = 0.f;

  float4 xv0, xv1, rv0, rv1;   // ASEL==1 prefetch registers

  // ---- prefetch A for chunk kc ----
  auto prefetchA = [&](int kc, uint32_t bufo) {
    if (ASEL == 1) {
      const int xrow = (int)((rowsPacked >> (5 * (kc >> 2))) & 31u);
      const float* xs = xb + xrow * 128 + (kc & 3) * 32;
      const float* rs = rb + kc * 32;
      xv0 = *(const float4*)(xs);
      xv1 = *(const float4*)(xs + 4);
      rv0 = *(const float4*)(rs);
      rv1 = *(const float4*)(rs + 4);
    } else {
      cp16(adH + bufo, h2h + kc * 32);
      cp16(adL + bufo, h2l + kc * 32);
    }
  };
  // ---- transform + store A regs (ASEL==1 only) ----
  auto storeA = [&](uint32_t bufo) {
    float p[8] = {xv0.x * rv0.x, xv0.y * rv0.y, xv0.z * rv0.z, xv0.w * rv0.w,
                  xv1.x * rv1.x, xv1.y * rv1.y, xv1.z * rv1.z, xv1.w * rv1.w};
    __align__(16) __nv_bfloat162 hh[4], ll[4];
#pragma unroll
    for (int u = 0; u < 4; ++u) {
      __nv_bfloat16 h0, l0, h1, l1;
      split2(p[2 * u], h0, l0);
      split2(p[2 * u + 1], h1, l1);
      hh[u] = __nv_bfloat162(h0, h1);
      ll[u] = __nv_bfloat162(l0, l1);
    }
    *(uint4*)(aHp + bufo) = *(const uint4*)hh;
    *(uint4*)(aLp + bufo) = *(const uint4*)ll;
  };
  auto stageW = [&](int kc, uint32_t bufo) {
    cp16(wdH + bufo, wh + kc * 32);
    cp16(wdL + bufo, wl + kc * 32);
  };
  auto compute = [&](uint32_t bufo) {
#pragma unroll
    for (int ks = 0; ks < 2; ++ks) {
      uint32_t Ah[2][4], Al[2][4];
#pragma unroll
      for (int m = 0; m < 2; ++m) {
        const char* p = sm + bufo + aoff + m * 1280 + ks * 32;
        Ah[m][0] = *(const uint32_t*)(p);
        Ah[m][1] = *(const uint32_t*)(p + 640);
        Ah[m][2] = *(const uint32_t*)(p + 16);
        Ah[m][3] = *(const uint32_t*)(p + 656);
        const char* q = p + T_AL;
        Al[m][0] = *(const uint32_t*)(q);
        Al[m][1] = *(const uint32_t*)(q + 640);
        Al[m][2] = *(const uint32_t*)(q + 16);
        Al[m][3] = *(const uint32_t*)(q + 656);
      }
#pragma unroll
      for (int n = 0; n < 4; ++n) {
        const char* pb = sm + bufo + boff + n * 640 + ks * 32;
        const uint32_t bh0 = *(const uint32_t*)(pb);
        const uint32_t bh1 = *(const uint32_t*)(pb + 16);
        const char* pl = pb + 10240;
        const uint32_t bl0 = *(const uint32_t*)(pl);
        const uint32_t bl1 = *(const uint32_t*)(pl + 16);
#pragma unroll
        for (int m = 0; m < 2; ++m) {
          mma16816(acc[m][n], Ah[m], bh0, bh1);
          mma16816(acc[m][n], Ah[m], bl0, bl1);
          mma16816(acc[m][n], Al[m], bh0, bh1);
        }
      }
    }
  };

  // prologue
  prefetchA(0, 0);
  stageW(0, 0);
  cp_commit();
  if (ASEL == 1) storeA(0);
  cp_wait0();
  __syncthreads();

  for (int kc = 0; kc < nch; ++kc) {
    const uint32_t bufo = (uint32_t)(kc & 1) * BUFB;
    const uint32_t nbufo = bufo ^ BUFB;
    const bool more = (kc + 1 < nch);
    if (more) {
      prefetchA(kc + 1, nbufo);
      stageW(kc + 1, nbufo);
      cp_commit();
    }
    compute(bufo);
    if (more) {
      cp_wait0();
      if (ASEL == 1) storeA(nbufo);
      __syncthreads();
    }
  }

  // epilogue
  float* op;
  int col0;
  const float* bp = nullptr;
  if (ASEL == 1) {
    op = outp;
    col0 = (int)((orowPack >> (5 * jb)) & 31u) * 128;
    if (bias) bp = bias + jb * 128;
  } else {
    op = g_rad;
    col0 = jb * 128;
    bp = bias + jb * 128;
  }
#pragma unroll
  for (int m = 0; m < 2; ++m) {
#pragma unroll
    for (int n = 0; n < 4; ++n) {
      const int col = wc * 32 + n * 8 + tg * 2;
      float b0v = 0.f, b1v = 0.f;
      if (bp) { b0v = bp[col]; b1v = bp[col + 1]; }
      const size_t rowA = e0 + wr * 32 + m * 16 + gq;
      float2 v0 = make_float2(acc[m][n][0] + b0v, acc[m][n][1] + b1v);
      float2 v1 = make_float2(acc[m][n][2] + b0v, acc[m][n][3] + b1v);
      *(float2*)(op + rowA * ostride + col0 + col) = v0;
      *(float2*)(op + (rowA + 8) * ostride + col0 + col) = v1;
    }
  }
}

// ============================================================================
// Radial MLP layers 1+2 (fused LN+SiLU), SIMT; writes split-bf16 h2.
// ============================================================================
__device__ __forceinline__ void zero_acc(float acc[4][8]) {
#pragma unroll
  for (int ee = 0; ee < 4; ++ee)
#pragma unroll
    for (int jj = 0; jj < 8; ++jj) acc[ee][jj] = 0.f;
}

__device__ __forceinline__ void rad_gemm128(const float* __restrict__ AT,
                                            const float* __restrict__ Wg,
                                            float* __restrict__ WS,
                                            float acc[4][8],
                                            int ty, int tx, int t)
{
  const int jL = t >> 1;
  const int kk0 = (t & 1) * 16;
  const float* wrow = Wg + jL * 128 + kk0;
#pragma unroll 1
  for (int kcu = 0; kcu < 4; ++kcu) {
#pragma unroll
    for (int u = 0; u < 4; ++u) {
      float4 v = *(const float4*)(wrow + kcu * 32 + u * 4);
      const int kk = kk0 + u * 4;
      WS[(kk + 0) * 132 + jL] = v.x;
      WS[(kk + 1) * 132 + jL] = v.y;
      WS[(kk + 2) * 132 + jL] = v.z;
      WS[(kk + 3) * 132 + jL] = v.w;
    }
    __syncthreads();
#pragma unroll
    for (int kk = 0; kk < 32; ++kk) {
      float4 a  = *(const float4*)(AT + (kcu * 32 + kk) * 68 + ty * 4);
      float4 b0 = *(const float4*)(WS + kk * 132 + tx * 8);
      float4 b1 = *(const float4*)(WS + kk * 132 + tx * 8 + 4);
      float av[4] = {a.x, a.y, a.z, a.w};
      float bv[8] = {b0.x, b0.y, b0.z, b0.w, b1.x, b1.y, b1.z, b1.w};
#pragma unroll
      for (int ee = 0; ee < 4; ++ee)
#pragma unroll
        for (int jj = 0; jj < 8; ++jj)
          acc[ee][jj] = fmaf(av[ee], bv[jj], acc[ee][jj]);
    }
    __syncthreads();
  }
}

__device__ __forceinline__ void store_bias_T(float* __restrict__ OT,
                                             const float acc[4][8],
                                             const float* __restrict__ bias,
                                             int ty, int tx)
{
  float4 q0 = *(const float4*)(bias + tx * 8);
  float4 q1 = *(const float4*)(bias + tx * 8 + 4);
  float bb[8] = {q0.x, q0.y, q0.z, q0.w, q1.x, q1.y, q1.z, q1.w};
#pragma unroll
  for (int jj = 0; jj < 8; ++jj) {
    const int j = tx * 8 + jj;
#pragma unroll
    for (int ee = 0; ee < 4; ++ee)
      OT[j * 68 + ty * 4 + ee] = acc[ee][jj] + bb[jj];
  }
}

__device__ __forceinline__ void ln_silu(float* __restrict__ HT,
                                        const float* __restrict__ g,
                                        const float* __restrict__ be, int t)
{
  const int e = t >> 2, q = t & 3;
  float vv[32];
  float s = 0.f, s2 = 0.f;
#pragma unroll
  for (int u = 0; u < 32; ++u) {
    float v = HT[(q * 32 + u) * 68 + e];
    vv[u] = v; s += v; s2 += v * v;
  }
  s  += __shfl_xor_sync(0xffffffffu, s, 1);
  s2 += __shfl_xor_sync(0xffffffffu, s2, 1);
  s  += __shfl_xor_sync(0xffffffffu, s, 2);
  s2 += __shfl_xor_sync(0xffffffffu, s2, 2);
  const float mu  = s * (1.0f / 128.0f);
  const float var = fmaf(-mu, mu, s2 * (1.0f / 128.0f));
  const float rin = rsqrtf(var + 1e-5f);
#pragma unroll
  for (int u = 0; u < 32; ++u) {
    const int j = q * 32 + u;
    float v = (vv[u] - mu) * rin * g[j] + be[j];
    v = v / (1.0f + expf(-v));
    HT[j * 68 + e] = v;
  }
}

__global__ __launch_bounds__(256)
void radial12_kernel(const float* __restrict__ xe,
                     const float* __restrict__ w1, const float* __restrict__ b1,
                     const float* __restrict__ g1, const float* __restrict__ be1,
                     const float* __restrict__ w2, const float* __restrict__ b2,
                     const float* __restrict__ g2, const float* __restrict__ be2)
{
  extern __shared__ float smx[];
  float* HA = smx;
  float* HB = smx + 128 * 68;
  float* WS = smx + 2 * 128 * 68;
  const int t = threadIdx.x;
  const int ty = t >> 4, tx = t & 15;
  const size_t e0 = (size_t)blockIdx.x * 64;

  {
    const int e = t >> 2, q = t & 3;
    const float* src = xe + (e0 + e) * 128 + q * 32;
#pragma unroll
    for (int u = 0; u < 8; ++u) {
      float4 v = *(const float4*)(src + u * 4);
      const int k = q * 32 + u * 4;
      HA[(k + 0) * 68 + e] = v.x;
      HA[(k + 1) * 68 + e] = v.y;
      HA[(k + 2) * 68 + e] = v.z;
      HA[(k + 3) * 68 + e] = v.w;
    }
  }
  __syncthreads();

  float acc[4][8];
  zero_acc(acc);
  rad_gemm128(HA, w1, WS, acc, ty, tx, t);
  store_bias_T(HB, acc, b1, ty, tx);
  __syncthreads();
  ln_silu(HB, g1, be1, t);
  __syncthreads();

  zero_acc(acc);
  rad_gemm128(HB, w2, WS, acc, ty, tx, t);
  store_bias_T(HA, acc, b2, ty, tx);
  __syncthreads();
  ln_silu(HA, g2, be2, t);

  // write split h2 (same thread wrote these elements in ln_silu -> no sync)
  {
    const int e = t >> 2, q = t & 3;
    __nv_bfloat16* dh = g_h2hi + (e0 + e) * 128 + q * 32;
    __nv_bfloat16* dl = g_h2lo + (e0 + e) * 128 + q * 32;
#pragma unroll
    for (int u = 0; u < 32; u += 2) {
      float v0 = HA[(q * 32 + u) * 68 + e];
      float v1 = HA[(q * 32 + u + 1) * 68 + e];
      __nv_bfloat16 h0, l0, h1, l1;
      split2(v0, h0, l0);
      split2(v1, h1, l1);
      *(__nv_bfloat162*)(dh + u) = __nv_bfloat162(h0, h1);
      *(__nv_bfloat162*)(dl + u) = __nv_bfloat162(l0, l1);
    }
  }
}

// ============================================================================
// weight split kernel
// ============================================================================
__global__ void convsplit_w(const float* __restrict__ s, int off, int n)
{
  int i = blockIdx.x * 256 + threadIdx.x;
  if (i < n) {
    __nv_bfloat16 h, l;
    split2(s[i], h, l);
    g_Whi[off + i] = h;
    g_Wlo[off + i] = l;
  }
}

// ---------------------------------------------------------------------------
static inline unsigned pk(int a, int b, int c, int d, int e)
{
  return (unsigned)a | ((unsigned)b << 5) | ((unsigned)c << 10) |
         ((unsigned)d << 15) | ((unsigned)e << 20);
}

extern "C" void kernel_launch(void* const* d_in, const int* in_sizes, int n_in,
                              void* d_out, int out_size)
{
  const float* x    = (const float*)d_in[0];
  const float* xe   = (const float*)d_in[1];
  const float* fc0w = (const float*)d_in[2];
  const float* fc0b = (const float*)d_in[3];
  const float* fc1w = (const float*)d_in[4];
  const float* fc2w = (const float*)d_in[5];
  const float* rw1  = (const float*)d_in[6];
  const float* rb1  = (const float*)d_in[7];
  const float* rg1  = (const float*)d_in[8];
  const float* rbe1 = (const float*)d_in[9];
  const float* rw2  = (const float*)d_in[10];
  const float* rb2  = (const float*)d_in[11];
  const float* rg2  = (const float*)d_in[12];
  const float* rbe2 = (const float*)d_in[13];
  const float* rw3  = (const float*)d_in[14];
  const float* rb3  = (const float*)d_in[15];
  float* out = (float*)d_out;

  const int N = in_sizes[1] / CH;
  const int nb64  = N / 64;
  const int nb128 = N / 128;

  // weight conversions
  convsplit_w<<<(409600 + 255) / 256, 256>>>(fc0w, W_FC0, 409600);
  convsplit_w<<<(262144 + 255) / 256, 256>>>(fc1w, W_FC1, 262144);
  convsplit_w<<<(147456 + 255) / 256, 256>>>(fc2w, W_FC2, 147456);
  convsplit_w<<<(196608 + 255) / 256, 256>>>(rw3, W_W3, 196608);

  // radial layers 1+2 (SIMT, fused LN+SiLU) -> split h2
  const int smem_r = (2 * 128 * 68 + 32 * 132) * 4;
  cudaFuncSetAttribute(radial12_kernel,
                       cudaFuncAttributeMaxDynamicSharedMemorySize, smem_r);
  radial12_kernel<<<nb64, 256, smem_r>>>(xe, rw1, rb1, rg1, rbe1,
                                         rw2, rb2, rg2, rbe2);

  cudaFuncSetAttribute(mma_gemm<0>,
                       cudaFuncAttributeMaxDynamicSharedMemorySize, SMEM_G);
  cudaFuncSetAttribute(mma_gemm<1>,
                       cudaFuncAttributeMaxDynamicSharedMemorySize, SMEM_G);

  // radial layer 3: g_rad = h2 @ w3^T + b3 (K=128, 12 output blocks of 128)
  mma_gemm<0><<<dim3(12, nb128), 512, SMEM_G>>>(
      nullptr, 0u, 0, W_W3, 128, rb3, nullptr, 1536, 0u);

  // SO2 GEMMs (jb fastest in grid -> concurrent CTAs share A via L2)
  mma_gemm<1><<<dim3(5, nb128), 512, SMEM_G>>>(
      x, pk(0, 2, 6, 11, 16), 0, W_FC0, 640, fc0b, out, KC * CH,
      pk(0, 2, 6, 11, 16));
  mma_gemm<1><<<dim3(4, nb128), 512, SMEM_G>>>(
      x, pk(3, 7, 12, 17, 0), 640, W_FC1, 512, nullptr, out, KC * CH,
      pk(3, 7, 12, 17, 0));
  mma_gemm<1><<<dim3(4, nb128), 512, SMEM_G>>>(
      x, pk(1, 5, 10, 15, 0), 640, W_FC1, 512, nullptr, out, KC * CH,
      pk(1, 5, 10, 15, 0));
  mma_gemm<1><<<dim3(3, nb128), 512, SMEM_G>>>(
      x, pk(8, 13, 18, 0, 0), 1152, W_FC2, 384, nullptr, out, KC * CH,
      pk(8, 13, 18, 0, 0));
  mma_gemm<1><<<dim3(3, nb128), 512, SMEM_G>>>(
      x, pk(4, 9, 14, 0, 0), 1152, W_FC2, 384, nullptr, out, KC * CH,
      pk(4, 9, 14, 0, 0));
}

// round 5
// speedup vs baseline: 3.6301x; 1.1564x over previous
#include <cuda_runtime.h>
#include <cuda_bf16.h>
#include <cstdint>

static constexpr int NE_MAX = 32768;
static constexpr int KC = 19;
static constexpr int CH = 128;
static constexpr int AW = 2432;

// weight segment offsets inside g_Whi/g_Wlo (elements)
static constexpr int W_FC0 = 0;                 // 640*640
static constexpr int W_FC1 = 409600;            // 512*512
static constexpr int W_FC2 = 671744;            // 384*384
static constexpr int W_W3  = 819200;            // 1536*128
static constexpr int W_TOT = 1015808;

// ------------------------- device scratch (no allocs allowed) ---------------
__device__ float g_rad[(size_t)NE_MAX * 1536];
__device__ __align__(16) __nv_bfloat16 g_h2hi[(size_t)NE_MAX * CH];
__device__ __align__(16) __nv_bfloat16 g_h2lo[(size_t)NE_MAX * CH];
__device__ __align__(16) __nv_bfloat16 g_Ahi[(size_t)NE_MAX * AW];
__device__ __align__(16) __nv_bfloat16 g_Alo[(size_t)NE_MAX * AW];
__device__ __align__(16) __nv_bfloat16 g_Whi[W_TOT];
__device__ __align__(16) __nv_bfloat16 g_Wlo[W_TOT];

// A-block -> x source row / rad column base (m-major expanded layout)
__constant__ int c_xrow[19] = {0,2,6,11,16, 3,7,12,17, 1,5,10,15, 8,13,18, 4,9,14};
__constant__ int c_radb[19] = {0,128,256,384,512, 640,768,896,1024,
                               640,768,896,1024, 1152,1280,1408, 1152,1280,1408};

// per-output-block GEMM config
struct Cfg { int acol0, K, wrow, col0, biasc, p0, p1, p2; };
__constant__ Cfg c_cfg[31] = {
  // --- SO2: fc0 (m=0), K=640, bias ---
  {0,    640, 0,      0,    0,   0,0,0},
  {0,    640, 81920,  256,  128, 0,0,0},
  {0,    640, 163840, 768,  256, 0,0,0},
  {0,    640, 245760, 1408, 384, 0,0,0},
  {0,    640, 327680, 2048, 512, 0,0,0},
  // --- fc1, +m rows {3,7,12,17} ---
  {640,  512, 409600, 384,  -1, 0,0,0},
  {640,  512, 475136, 896,  -1, 0,0,0},
  {640,  512, 540672, 1536, -1, 0,0,0},
  {640,  512, 606208, 2176, -1, 0,0,0},
  // --- fc1, -m rows {1,5,10,15} ---
  {1152, 512, 409600, 128,  -1, 0,0,0},
  {1152, 512, 475136, 640,  -1, 0,0,0},
  {1152, 512, 540672, 1280, -1, 0,0,0},
  {1152, 512, 606208, 1920, -1, 0,0,0},
  // --- fc2, +m rows {8,13,18} ---
  {1664, 384, 671744, 1024, -1, 0,0,0},
  {1664, 384, 720896, 1664, -1, 0,0,0},
  {1664, 384, 770048, 2304, -1, 0,0,0},
  // --- fc2, -m rows {4,9,14} ---
  {2048, 384, 671744, 512,  -1, 0,0,0},
  {2048, 384, 720896, 1152, -1, 0,0,0},
  {2048, 384, 770048, 1792, -1, 0,0,0},
  // --- w3 (radial layer 3), 12 blocks, K=128, bias=rb3 ---
  {0, 128, 819200,  0,    0,    0,0,0},
  {0, 128, 835584,  128,  128,  0,0,0},
  {0, 128, 851968,  256,  256,  0,0,0},
  {0, 128, 868352,  384,  384,  0,0,0},
  {0, 128, 884736,  512,  512,  0,0,0},
  {0, 128, 901120,  640,  640,  0,0,0},
  {0, 128, 917504,  768,  768,  0,0,0},
  {0, 128, 933888,  896,  896,  0,0,0},
  {0, 128, 950272,  1024, 1024, 0,0,0},
  {0, 128, 966656,  1152, 1152, 0,0,0},
  {0, 128, 983040,  1280, 1280, 0,0,0},
  {0, 128, 999424,  1408, 1408, 0,0,0},
};

// ------------------------- helpers ------------------------------------------
__device__ __forceinline__ uint32_t smem_u32(const void* p) {
  uint32_t a;
  asm("{ .reg .u64 t; cvta.to.shared.u64 t, %1; cvt.u32.u64 %0, t; }"
      : "=r"(a) : "l"(p));
  return a;
}
__device__ __forceinline__ void cp16(uint32_t dst, const void* src) {
  asm volatile("cp.async.cg.shared.global [%0], [%1], 16;" :: "r"(dst), "l"(src));
}
__device__ __forceinline__ void cp_commit() {
  asm volatile("cp.async.commit_group;");
}
__device__ __forceinline__ void cp_wait0() {
  asm volatile("cp.async.wait_group 0;" ::: "memory");
}
__device__ __forceinline__ void ldsm4(uint32_t* r, uint32_t a) {
  asm volatile("ldmatrix.sync.aligned.m8n8.x4.shared.b16 {%0,%1,%2,%3}, [%4];"
               : "=r"(r[0]), "=r"(r[1]), "=r"(r[2]), "=r"(r[3]) : "r"(a));
}
__device__ __forceinline__ void mma16816(float* c, const uint32_t* a,
                                         uint32_t b0, uint32_t b1) {
  asm volatile(
      "mma.sync.aligned.m16n8k16.row.col.f32.bf16.bf16.f32 "
      "{%0,%1,%2,%3}, {%4,%5,%6,%7}, {%8,%9}, {%0,%1,%2,%3};"
      : "+f"(c[0]), "+f"(c[1]), "+f"(c[2]), "+f"(c[3])
      : "r"(a[0]), "r"(a[1]), "r"(a[2]), "r"(a[3]), "r"(b0), "r"(b1));
}
__device__ __forceinline__ void split2(float v, __nv_bfloat16& h, __nv_bfloat16& l) {
  h = __float2bfloat16(v);
  l = __float2bfloat16(v - __bfloat162float(h));
}

// smem per buffer: AH 0, AL 10240, WH 20480, WL 30720; [128 rows][32 k] bf16,
// row pitch 40 elems (80 B).
static constexpr int T_AL = 10240, T_WH = 20480, T_WL = 30720;
static constexpr int BUFB = 40960;
static constexpr int SMEM_G = 2 * BUFB;   // 81920

// ============================================================================
// Unified GEMM: D[128 edges x 128 out] = Ahi/Alo @ Whi/Wlo^T (3-term split),
// all operands bf16, cp.async staged, ldmatrix fragments.
// asel: 1 -> A = g_Ahi/g_Alo (stride AW); 0 -> A = g_h2hi/g_h2lo (stride 128).
// outp == nullptr -> write g_rad (device symbol resolved in device code).
// 256 threads, 2 CTAs/SM, warp tile 32x64.
// ============================================================================
__global__ void __launch_bounds__(256, 2)
mma_gemm(int asel, const float* __restrict__ bias,
         float* __restrict__ outp, int ostride, int cfg0)
{
  extern __shared__ char sm[];
  const Cfg cfg = c_cfg[cfg0 + blockIdx.x];
  const int K = cfg.K;
  const int t = threadIdx.x;
  const size_t e0 = (size_t)blockIdx.y * 128;
  const uint32_t sb = smem_u32(sm);

  // device-side selection of A operand (device symbols NOT valid from host!)
  const __nv_bfloat16* __restrict__ Ahi = asel ? g_Ahi : g_h2hi;
  const __nv_bfloat16* __restrict__ Alo = asel ? g_Alo : g_h2lo;
  const int astride = asel ? AW : 128;
  float* __restrict__ op = outp ? outp : g_rad;

  // ---- staging mapping: 2 threads per row, 32 B (16 elems) per thread ----
  const int srow = t >> 1, sh = t & 1;
  const __nv_bfloat16* gah =
      Ahi + (e0 + srow) * (size_t)astride + cfg.acol0 + sh * 16;
  const __nv_bfloat16* gal =
      Alo + (e0 + srow) * (size_t)astride + cfg.acol0 + sh * 16;
  const __nv_bfloat16* gwh = g_Whi + cfg.wrow + (size_t)srow * K + sh * 16;
  const __nv_bfloat16* gwl = g_Wlo + cfg.wrow + (size_t)srow * K + sh * 16;
  const uint32_t sdst = sb + srow * 80 + sh * 32;

  // ---- compute mapping: 8 warps as 4 (rows) x 2 (cols); tile 32x64 ----
  const int wid = t >> 5, lane = t & 31;
  const int wr = wid & 3, wc = wid >> 2;
  const int lm = lane >> 3, lr = lane & 7;        // ldmatrix matrix id, row
  const int arow  = wr * 32 + ((lm & 1) ? 8 : 0) + lr;
  const int akoff = (lm & 2) ? 16 : 0;
  const int brow0 = wc * 64 + ((lm & 2) ? 8 : 0) + lr;
  const int bkoff = (lm & 1) ? 16 : 0;
  const int gq = lane >> 2, tg = lane & 3;

  float acc[2][8][4];
#pragma unroll
  for (int m = 0; m < 2; ++m)
#pragma unroll
    for (int n = 0; n < 8; ++n)
#pragma unroll
      for (int u = 0; u < 4; ++u) acc[m][n][u] = 0.f;

  auto stage = [&](int kc, uint32_t bo) {
    const __nv_bfloat16* p;
    p = gah + kc * 32; cp16(sdst + bo, p);          cp16(sdst + bo + 16, p + 8);
    p = gal + kc * 32; cp16(sdst + bo + T_AL, p);   cp16(sdst + bo + T_AL + 16, p + 8);
    p = gwh + kc * 32; cp16(sdst + bo + T_WH, p);   cp16(sdst + bo + T_WH + 16, p + 8);
    p = gwl + kc * 32; cp16(sdst + bo + T_WL, p);   cp16(sdst + bo + T_WL + 16, p + 8);
  };

  auto compute = [&](uint32_t bo) {
#pragma unroll
    for (int ks = 0; ks < 2; ++ks) {
      uint32_t Ah[2][4], Al[2][4];
#pragma unroll
      for (int m = 0; m < 2; ++m) {
        const uint32_t aa = sb + bo + (uint32_t)(arow + m * 16) * 80 + akoff + ks * 32;
        ldsm4(Ah[m], aa);
        ldsm4(Al[m], aa + T_AL);
      }
#pragma unroll
      for (int n2 = 0; n2 < 4; ++n2) {
        const uint32_t ba =
            sb + bo + T_WH + (uint32_t)(brow0 + n2 * 16) * 80 + bkoff + ks * 32;
        uint32_t Bh[4], Bl[4];
        ldsm4(Bh, ba);
        ldsm4(Bl, ba + 10240);
#pragma unroll
        for (int m = 0; m < 2; ++m) {
          mma16816(acc[m][2 * n2],     Ah[m], Bh[0], Bh[1]);
          mma16816(acc[m][2 * n2],     Ah[m], Bl[0], Bl[1]);
          mma16816(acc[m][2 * n2],     Al[m], Bh[0], Bh[1]);
          mma16816(acc[m][2 * n2 + 1], Ah[m], Bh[2], Bh[3]);
          mma16816(acc[m][2 * n2 + 1], Ah[m], Bl[2], Bl[3]);
          mma16816(acc[m][2 * n2 + 1], Al[m], Bh[2], Bh[3]);
        }
      }
    }
  };

  const int nch = K >> 5;

  // prologue
  stage(0, 0);
  cp_commit();
  cp_wait0();
  __syncthreads();

  for (int kc = 0; kc < nch; ++kc) {
    const uint32_t bo = (uint32_t)(kc & 1) * BUFB;
    const bool more = (kc + 1 < nch);
    if (more) {
      stage(kc + 1, bo ^ BUFB);
      cp_commit();
    }
    compute(bo);
    if (more) {
      cp_wait0();
      __syncthreads();
    }
  }

  // epilogue
  const float* bp = (cfg.biasc >= 0) ? bias + cfg.biasc : nullptr;
#pragma unroll
  for (int m = 0; m < 2; ++m) {
#pragma unroll
    for (int n = 0; n < 8; ++n) {
      const int col = wc * 64 + n * 8 + tg * 2;
      float b0v = 0.f, b1v = 0.f;
      if (bp) { b0v = bp[col]; b1v = bp[col + 1]; }
      const size_t row = e0 + wr * 32 + m * 16 + gq;
      float* d0 = op + row * (size_t)ostride + cfg.col0 + col;
      float* d1 = d0 + 8 * (size_t)ostride;
      *(float2*)d0 = make_float2(acc[m][n][0] + b0v, acc[m][n][1] + b1v);
      *(float2*)d1 = make_float2(acc[m][n][2] + b0v, acc[m][n][3] + b1v);
    }
  }
}

// ============================================================================
// Radial MLP layers 1+2 (fused LN+SiLU), SIMT; writes split-bf16 h2.
// ============================================================================
__device__ __forceinline__ void zero_acc8(float acc[4][8]) {
#pragma unroll
  for (int ee = 0; ee < 4; ++ee)
#pragma unroll
    for (int jj = 0; jj < 8; ++jj) acc[ee][jj] = 0.f;
}

__device__ __forceinline__ void rad_gemm128(const float* __restrict__ AT,
                                            const float* __restrict__ Wg,
                                            float* __restrict__ WS,
                                            float acc[4][8],
                                            int ty, int tx, int t)
{
  const int jL = t >> 1;
  const int kk0 = (t & 1) * 16;
  const float* wrow = Wg + jL * 128 + kk0;
#pragma unroll 1
  for (int kcu = 0; kcu < 4; ++kcu) {
#pragma unroll
    for (int u = 0; u < 4; ++u) {
      float4 v = *(const float4*)(wrow + kcu * 32 + u * 4);
      const int kk = kk0 + u * 4;
      WS[(kk + 0) * 132 + jL] = v.x;
      WS[(kk + 1) * 132 + jL] = v.y;
      WS[(kk + 2) * 132 + jL] = v.z;
      WS[(kk + 3) * 132 + jL] = v.w;
    }
    __syncthreads();
#pragma unroll
    for (int kk = 0; kk < 32; ++kk) {
      float4 a  = *(const float4*)(AT + (kcu * 32 + kk) * 68 + ty * 4);
      float4 b0 = *(const float4*)(WS + kk * 132 + tx * 8);
      float4 b1 = *(const float4*)(WS + kk * 132 + tx * 8 + 4);
      float av[4] = {a.x, a.y, a.z, a.w};
      float bv[8] = {b0.x, b0.y, b0.z, b0.w, b1.x, b1.y, b1.z, b1.w};
#pragma unroll
      for (int ee = 0; ee < 4; ++ee)
#pragma unroll
        for (int jj = 0; jj < 8; ++jj)
          acc[ee][jj] = fmaf(av[ee], bv[jj], acc[ee][jj]);
    }
    __syncthreads();
  }
}

__device__ __forceinline__ void store_bias_T(float* __restrict__ OT,
                                             const float acc[4][8],
                                             const float* __restrict__ bias,
                                             int ty, int tx)
{
  float4 q0 = *(const float4*)(bias + tx * 8);
  float4 q1 = *(const float4*)(bias + tx * 8 + 4);
  float bb[8] = {q0.x, q0.y, q0.z, q0.w, q1.x, q1.y, q1.z, q1.w};
#pragma unroll
  for (int jj = 0; jj < 8; ++jj) {
    const int j = tx * 8 + jj;
#pragma unroll
    for (int ee = 0; ee < 4; ++ee)
      OT[j * 68 + ty * 4 + ee] = acc[ee][jj] + bb[jj];
  }
}

__device__ __forceinline__ void ln_silu(float* __restrict__ HT,
                                        const float* __restrict__ g,
                                        const float* __restrict__ be, int t)
{
  const int e = t >> 2, q = t & 3;
  float vv[32];
  float s = 0.f, s2 = 0.f;
#pragma unroll
  for (int u = 0; u < 32; ++u) {
    float v = HT[(q * 32 + u) * 68 + e];
    vv[u] = v; s += v; s2 += v * v;
  }
  s  += __shfl_xor_sync(0xffffffffu, s, 1);
  s2 += __shfl_xor_sync(0xffffffffu, s2, 1);
  s  += __shfl_xor_sync(0xffffffffu, s, 2);
  s2 += __shfl_xor_sync(0xffffffffu, s2, 2);
  const float mu  = s * (1.0f / 128.0f);
  const float var = fmaf(-mu, mu, s2 * (1.0f / 128.0f));
  const float rin = rsqrtf(var + 1e-5f);
#pragma unroll
  for (int u = 0; u < 32; ++u) {
    const int j = q * 32 + u;
    float v = (vv[u] - mu) * rin * g[j] + be[j];
    v = v / (1.0f + expf(-v));
    HT[j * 68 + e] = v;
  }
}

__global__ __launch_bounds__(256)
void radial12_kernel(const float* __restrict__ xe,
                     const float* __restrict__ w1, const float* __restrict__ b1,
                     const float* __restrict__ g1, const float* __restrict__ be1,
                     const float* __restrict__ w2, const float* __restrict__ b2,
                     const float* __restrict__ g2, const float* __restrict__ be2)
{
  extern __shared__ float smx[];
  float* HA = smx;
  float* HB = smx + 128 * 68;
  float* WS = smx + 2 * 128 * 68;
  const int t = threadIdx.x;
  const int ty = t >> 4, tx = t & 15;
  const size_t e0 = (size_t)blockIdx.x * 64;

  {
    const int e = t >> 2, q = t & 3;
    const float* src = xe + (e0 + e) * 128 + q * 32;
#pragma unroll
    for (int u = 0; u < 8; ++u) {
      float4 v = *(const float4*)(src + u * 4);
      const int k = q * 32 + u * 4;
      HA[(k + 0) * 68 + e] = v.x;
      HA[(k + 1) * 68 + e] = v.y;
      HA[(k + 2) * 68 + e] = v.z;
      HA[(k + 3) * 68 + e] = v.w;
    }
  }
  __syncthreads();

  float acc[4][8];
  zero_acc8(acc);
  rad_gemm128(HA, w1, WS, acc, ty, tx, t);
  store_bias_T(HB, acc, b1, ty, tx);
  __syncthreads();
  ln_silu(HB, g1, be1, t);
  __syncthreads();

  zero_acc8(acc);
  rad_gemm128(HB, w2, WS, acc, ty, tx, t);
  store_bias_T(HA, acc, b2, ty, tx);
  __syncthreads();
  ln_silu(HA, g2, be2, t);

  // write split h2 (same thread wrote these elements in ln_silu -> no sync)
  {
    const int e = t >> 2, q = t & 3;
    __nv_bfloat16* dh = g_h2hi + (e0 + e) * 128 + q * 32;
    __nv_bfloat16* dl = g_h2lo + (e0 + e) * 128 + q * 32;
#pragma unroll
    for (int u = 0; u < 32; u += 2) {
      float v0 = HA[(q * 32 + u) * 68 + e];
      float v1 = HA[(q * 32 + u + 1) * 68 + e];
      __nv_bfloat16 h0, l0, h1, l1;
      split2(v0, h0, l0);
      split2(v1, h1, l1);
      *(__nv_bfloat162*)(dh + u) = __nv_bfloat162(h0, h1);
      *(__nv_bfloat162*)(dl + u) = __nv_bfloat162(l0, l1);
    }
  }
}

// ============================================================================
// prep kernels
// ============================================================================
__global__ void convsplit_w(const float* __restrict__ s, int off, int n)
{
  int i = blockIdx.x * 256 + threadIdx.x;
  if (i < n) {
    __nv_bfloat16 h, l;
    split2(s[i], h, l);
    g_Whi[off + i] = h;
    g_Wlo[off + i] = l;
  }
}

// A[e, col] = x[e, xrow(blk)*128 + c] * rad[e, radb(blk) + c], split to bf16
__global__ void prep_A(const float* __restrict__ x, int total)
{
  int idx = blockIdx.x * 256 + threadIdx.x;   // one thread = 4 cols
  if (idx >= total) return;
  const int q = idx % 608;
  const size_t e = (size_t)(idx / 608);
  const int col = q * 4;
  const int blk = col >> 7, c = col & 127;
  const float4 xv = *(const float4*)(x + e * AW + c_xrow[blk] * 128 + c);
  const float4 rv = *(const float4*)(g_rad + e * 1536 + c_radb[blk] + c);
  float v[4] = {xv.x * rv.x, xv.y * rv.y, xv.z * rv.z, xv.w * rv.w};
  __nv_bfloat16 h[4], l[4];
#pragma unroll
  for (int u = 0; u < 4; ++u) split2(v[u], h[u], l[u]);
  __nv_bfloat162 hh[2] = {__nv_bfloat162(h[0], h[1]), __nv_bfloat162(h[2], h[3])};
  __nv_bfloat162 ll[2] = {__nv_bfloat162(l[0], l[1]), __nv_bfloat162(l[2], l[3])};
  *(uint2*)(g_Ahi + e * AW + col) = *(uint2*)hh;
  *(uint2*)(g_Alo + e * AW + col) = *(uint2*)ll;
}

// ---------------------------------------------------------------------------
extern "C" void kernel_launch(void* const* d_in, const int* in_sizes, int n_in,
                              void* d_out, int out_size)
{
  const float* x    = (const float*)d_in[0];
  const float* xe   = (const float*)d_in[1];
  const float* fc0w = (const float*)d_in[2];
  const float* fc0b = (const float*)d_in[3];
  const float* fc1w = (const float*)d_in[4];
  const float* fc2w = (const float*)d_in[5];
  const float* rw1  = (const float*)d_in[6];
  const float* rb1  = (const float*)d_in[7];
  const float* rg1  = (const float*)d_in[8];
  const float* rbe1 = (const float*)d_in[9];
  const float* rw2  = (const float*)d_in[10];
  const float* rb2  = (const float*)d_in[11];
  const float* rg2  = (const float*)d_in[12];
  const float* rbe2 = (const float*)d_in[13];
  const float* rw3  = (const float*)d_in[14];
  const float* rb3  = (const float*)d_in[15];
  float* out = (float*)d_out;

  const int N = in_sizes[1] / CH;
  const int nb64  = N / 64;
  const int nb128 = N / 128;

  // weight conversions
  convsplit_w<<<(409600 + 255) / 256, 256>>>(fc0w, W_FC0, 409600);
  convsplit_w<<<(262144 + 255) / 256, 256>>>(fc1w, W_FC1, 262144);
  convsplit_w<<<(147456 + 255) / 256, 256>>>(fc2w, W_FC2, 147456);
  convsplit_w<<<(196608 + 255) / 256, 256>>>(rw3, W_W3, 196608);

  // radial layers 1+2 (SIMT, fused LN+SiLU) -> split h2
  const int smem_r = (2 * 128 * 68 + 32 * 132) * 4;
  cudaFuncSetAttribute(radial12_kernel,
                       cudaFuncAttributeMaxDynamicSharedMemorySize, smem_r);
  radial12_kernel<<<nb64, 256, smem_r>>>(xe, rw1, rb1, rg1, rbe1,
                                         rw2, rb2, rg2, rbe2);

  cudaFuncSetAttribute(mma_gemm,
                       cudaFuncAttributeMaxDynamicSharedMemorySize, SMEM_G);

  // radial layer 3: g_rad = h2 @ w3^T + b3  (12 blocks, K=128, cfg 19..30)
  // outp=nullptr -> kernel writes g_rad (device symbol resolved on device)
  mma_gemm<<<dim3(12, nb128), 256, SMEM_G>>>(0, rb3, nullptr, 1536, 19);

  // A = gathered x * rad, split to bf16
  prep_A<<<(N * 608 + 255) / 256, 256>>>(x, N * 608);

  // all 19 SO2 output blocks in ONE launch (cfg 0..18)
  mma_gemm<<<dim3(19, nb128), 256, SMEM_G>>>(1, fc0b, out, KC * CH, 0);
}

// round 6
// speedup vs baseline: 3.6933x; 1.0174x over previous
#include <cuda_runtime.h>
#include <cuda_bf16.h>
#include <cstdint>

static constexpr int NE_MAX = 32768;
static constexpr int KC = 19;
static constexpr int CH = 128;
static constexpr int AW = 2432;

// weight segment offsets inside g_Whi/g_Wlo (elements)
static constexpr int W_FC0 = 0;                 // 640*640
static constexpr int W_FC1 = 409600;            // 512*512
static constexpr int W_FC2 = 671744;            // 384*384
static constexpr int W_W3  = 819200;            // 1536*128
static constexpr int W_TOT = 1015808;

// ------------------------- device scratch (no allocs allowed) ---------------
__device__ __align__(16) __nv_bfloat16 g_h2hi[(size_t)NE_MAX * CH];
__device__ __align__(16) __nv_bfloat16 g_h2lo[(size_t)NE_MAX * CH];
__device__ __align__(16) __nv_bfloat16 g_Ahi[(size_t)NE_MAX * AW];
__device__ __align__(16) __nv_bfloat16 g_Alo[(size_t)NE_MAX * AW];
__device__ __align__(16) __nv_bfloat16 g_Whi[W_TOT];
__device__ __align__(16) __nv_bfloat16 g_Wlo[W_TOT];

// A-block -> x source row (m-major expanded layout)
__constant__ int c_xrow[19] = {0,2,6,11,16, 3,7,12,17, 1,5,10,15, 8,13,18, 4,9,14};

// per-output-block GEMM config
struct Cfg { int acol0, K, wrow, col0, biasc, p0, p1, p2; };
__constant__ Cfg c_cfg[31] = {
  // --- SO2: fc0 (m=0), K=640, bias ---
  {0,    640, 0,      0,    0,   0,0,0},
  {0,    640, 81920,  256,  128, 0,0,0},
  {0,    640, 163840, 768,  256, 0,0,0},
  {0,    640, 245760, 1408, 384, 0,0,0},
  {0,    640, 327680, 2048, 512, 0,0,0},
  // --- fc1, +m rows {3,7,12,17} ---
  {640,  512, 409600, 384,  -1, 0,0,0},
  {640,  512, 475136, 896,  -1, 0,0,0},
  {640,  512, 540672, 1536, -1, 0,0,0},
  {640,  512, 606208, 2176, -1, 0,0,0},
  // --- fc1, -m rows {1,5,10,15} ---
  {1152, 512, 409600, 128,  -1, 0,0,0},
  {1152, 512, 475136, 640,  -1, 0,0,0},
  {1152, 512, 540672, 1280, -1, 0,0,0},
  {1152, 512, 606208, 1920, -1, 0,0,0},
  // --- fc2, +m rows {8,13,18} ---
  {1664, 384, 671744, 1024, -1, 0,0,0},
  {1664, 384, 720896, 1664, -1, 0,0,0},
  {1664, 384, 770048, 2304, -1, 0,0,0},
  // --- fc2, -m rows {4,9,14} ---
  {2048, 384, 671744, 512,  -1, 0,0,0},
  {2048, 384, 720896, 1152, -1, 0,0,0},
  {2048, 384, 770048, 1792, -1, 0,0,0},
  // --- w3 (radial layer 3), 12 blocks, K=128, bias=rb3, fused FiLM+split ---
  {0, 128, 819200,  0,    0,    0,0,0},
  {0, 128, 835584,  128,  128,  0,0,0},
  {0, 128, 851968,  256,  256,  0,0,0},
  {0, 128, 868352,  384,  384,  0,0,0},
  {0, 128, 884736,  512,  512,  0,0,0},
  {0, 128, 901120,  640,  640,  0,0,0},
  {0, 128, 917504,  768,  768,  0,0,0},
  {0, 128, 933888,  896,  896,  0,0,0},
  {0, 128, 950272,  1024, 1024, 0,0,0},
  {0, 128, 966656,  1152, 1152, 0,0,0},
  {0, 128, 983040,  1280, 1280, 0,0,0},
  {0, 128, 999424,  1408, 1408, 0,0,0},
};

// ------------------------- helpers ------------------------------------------
__device__ __forceinline__ uint32_t smem_u32(const void* p) {
  uint32_t a;
  asm("{ .reg .u64 t; cvta.to.shared.u64 t, %1; cvt.u32.u64 %0, t; }"
      : "=r"(a) : "l"(p));
  return a;
}
__device__ __forceinline__ void cp16(uint32_t dst, const void* src) {
  asm volatile("cp.async.cg.shared.global [%0], [%1], 16;" :: "r"(dst), "l"(src));
}
__device__ __forceinline__ void cp_commit() {
  asm volatile("cp.async.commit_group;");
}
__device__ __forceinline__ void cp_wait0() {
  asm volatile("cp.async.wait_group 0;" ::: "memory");
}
__device__ __forceinline__ void ldsm4(uint32_t* r, uint32_t a) {
  asm volatile("ldmatrix.sync.aligned.m8n8.x4.shared.b16 {%0,%1,%2,%3}, [%4];"
               : "=r"(r[0]), "=r"(r[1]), "=r"(r[2]), "=r"(r[3]) : "r"(a));
}
__device__ __forceinline__ void mma16816(float* c, const uint32_t* a,
                                         uint32_t b0, uint32_t b1) {
  asm volatile(
      "mma.sync.aligned.m16n8k16.row.col.f32.bf16.bf16.f32 "
      "{%0,%1,%2,%3}, {%4,%5,%6,%7}, {%8,%9}, {%0,%1,%2,%3};"
      : "+f"(c[0]), "+f"(c[1]), "+f"(c[2]), "+f"(c[3])
      : "r"(a[0]), "r"(a[1]), "r"(a[2]), "r"(a[3]), "r"(b0), "r"(b1));
}
__device__ __forceinline__ void split2(float v, __nv_bfloat16& h, __nv_bfloat16& l) {
  h = __float2bfloat16(v);
  l = __float2bfloat16(v - __bfloat162float(h));
}

// smem per buffer: AH 0, AL 10240, WH 20480, WL 30720; [128 rows][32 k] bf16,
// row pitch 40 elems (80 B).
static constexpr int T_AL = 10240, T_WH = 20480, T_WL = 30720;
static constexpr int BUFB = 40960;
static constexpr int SMEM_G = 2 * BUFB;   // 81920

// ============================================================================
// Unified GEMM: D[128 edges x 128 out] = Ahi/Alo @ Whi/Wlo^T (3-term split).
// mode 0: A = g_Ahi/g_Alo (stride AW), normal epilogue -> outp (+bias).
// mode 1: A = g_h2hi/g_h2lo (stride 128); epilogue computes rad = D + bias,
//         then FiLM-multiplies gathered x rows and writes split-bf16 g_Ahi/g_Alo
//         (fused radial-layer-3 + prep_A; ±m blocks share this rad slice).
// 256 threads, 2 CTAs/SM, warp tile 32x64.
// ============================================================================
__global__ void __launch_bounds__(256, 2)
mma_gemm(int mode, const float* __restrict__ bias,
         const float* __restrict__ xg,
         float* __restrict__ outp, int ostride, int cfg0)
{
  extern __shared__ char sm[];
  const Cfg cfg = c_cfg[cfg0 + blockIdx.x];
  const int K = cfg.K;
  const int t = threadIdx.x;
  const size_t e0 = (size_t)blockIdx.y * 128;
  const uint32_t sb = smem_u32(sm);

  // device-side A operand selection (device symbols invalid from host!)
  const __nv_bfloat16* __restrict__ Ahi = (mode == 1) ? g_h2hi : g_Ahi;
  const __nv_bfloat16* __restrict__ Alo = (mode == 1) ? g_h2lo : g_Alo;
  const int astride = (mode == 1) ? 128 : AW;

  // ---- staging mapping: 2 threads per row, 32 B (16 elems) per thread ----
  const int srow = t >> 1, sh = t & 1;
  const __nv_bfloat16* gah =
      Ahi + (e0 + srow) * (size_t)astride + cfg.acol0 + sh * 16;
  const __nv_bfloat16* gal =
      Alo + (e0 + srow) * (size_t)astride + cfg.acol0 + sh * 16;
  const __nv_bfloat16* gwh = g_Whi + cfg.wrow + (size_t)srow * K + sh * 16;
  const __nv_bfloat16* gwl = g_Wlo + cfg.wrow + (size_t)srow * K + sh * 16;
  const uint32_t sdst = sb + srow * 80 + sh * 32;

  // ---- compute mapping: 8 warps as 4 (rows) x 2 (cols); tile 32x64 ----
  const int wid = t >> 5, lane = t & 31;
  const int wr = wid & 3, wc = wid >> 2;
  const int lm = lane >> 3, lr = lane & 7;        // ldmatrix matrix id, row
  const int arow  = wr * 32 + ((lm & 1) ? 8 : 0) + lr;
  const int akoff = (lm & 2) ? 16 : 0;
  const int brow0 = wc * 64 + ((lm & 2) ? 8 : 0) + lr;
  const int bkoff = (lm & 1) ? 16 : 0;
  const int gq = lane >> 2, tg = lane & 3;

  float acc[2][8][4];
#pragma unroll
  for (int m = 0; m < 2; ++m)
#pragma unroll
    for (int n = 0; n < 8; ++n)
#pragma unroll
      for (int u = 0; u < 4; ++u) acc[m][n][u] = 0.f;

  auto stage = [&](int kc, uint32_t bo) {
    const __nv_bfloat16* p;
    p = gah + kc * 32; cp16(sdst + bo, p);          cp16(sdst + bo + 16, p + 8);
    p = gal + kc * 32; cp16(sdst + bo + T_AL, p);   cp16(sdst + bo + T_AL + 16, p + 8);
    p = gwh + kc * 32; cp16(sdst + bo + T_WH, p);   cp16(sdst + bo + T_WH + 16, p + 8);
    p = gwl + kc * 32; cp16(sdst + bo + T_WL, p);   cp16(sdst + bo + T_WL + 16, p + 8);
  };

  auto compute = [&](uint32_t bo) {
#pragma unroll
    for (int ks = 0; ks < 2; ++ks) {
      uint32_t Ah[2][4], Al[2][4];
#pragma unroll
      for (int m = 0; m < 2; ++m) {
        const uint32_t aa = sb + bo + (uint32_t)(arow + m * 16) * 80 + akoff + ks * 32;
        ldsm4(Ah[m], aa);
        ldsm4(Al[m], aa + T_AL);
      }
#pragma unroll
      for (int n2 = 0; n2 < 4; ++n2) {
        const uint32_t ba =
            sb + bo + T_WH + (uint32_t)(brow0 + n2 * 16) * 80 + bkoff + ks * 32;
        uint32_t Bh[4], Bl[4];
        ldsm4(Bh, ba);
        ldsm4(Bl, ba + 10240);
#pragma unroll
        for (int m = 0; m < 2; ++m) {
          mma16816(acc[m][2 * n2],     Ah[m], Bh[0], Bh[1]);
          mma16816(acc[m][2 * n2],     Ah[m], Bl[0], Bl[1]);
          mma16816(acc[m][2 * n2],     Al[m], Bh[0], Bh[1]);
          mma16816(acc[m][2 * n2 + 1], Ah[m], Bh[2], Bh[3]);
          mma16816(acc[m][2 * n2 + 1], Ah[m], Bl[2], Bl[3]);
          mma16816(acc[m][2 * n2 + 1], Al[m], Bh[2], Bh[3]);
        }
      }
    }
  };

  const int nch = K >> 5;

  // prologue
  stage(0, 0);
  cp_commit();
  cp_wait0();
  __syncthreads();

  for (int kc = 0; kc < nch; ++kc) {
    const uint32_t bo = (uint32_t)(kc & 1) * BUFB;
    const bool more = (kc + 1 < nch);
    if (more) {
      stage(kc + 1, bo ^ BUFB);
      cp_commit();
    }
    compute(bo);
    if (more) {
      cp_wait0();
      __syncthreads();
    }
  }

  if (mode == 1) {
    // ---- fused epilogue: rad = D + bias; A = x_gather * rad, split bf16 ----
    const int jb = blockIdx.x;                    // 0..11 rad block
    int tb0, tb1;
    if (jb < 5)      { tb0 = jb;     tb1 = -1;     }   // m = 0
    else if (jb < 9) { tb0 = jb;     tb1 = jb + 4; }   // m = 1 (+m, -m)
    else             { tb0 = jb + 4; tb1 = jb + 7; }   // m = 2 (+m, -m)
    const float* bp = bias + cfg.biasc;
#pragma unroll
    for (int m = 0; m < 2; ++m) {
#pragma unroll
      for (int n = 0; n < 8; ++n) {
        const int col = wc * 64 + n * 8 + tg * 2;
        const float b0v = bp[col], b1v = bp[col + 1];
        const size_t r0 = e0 + wr * 32 + m * 16 + gq;
        const size_t r1 = r0 + 8;
        const float rv00 = acc[m][n][0] + b0v, rv01 = acc[m][n][1] + b1v;
        const float rv10 = acc[m][n][2] + b0v, rv11 = acc[m][n][3] + b1v;
#pragma unroll
        for (int tt = 0; tt < 2; ++tt) {
          const int tb = tt ? tb1 : tb0;
          if (tb < 0) continue;
          const int xr = c_xrow[tb];
          const float2 x0 = *(const float2*)(xg + r0 * AW + xr * 128 + col);
          const float2 x1 = *(const float2*)(xg + r1 * AW + xr * 128 + col);
          __nv_bfloat16 h0, l0, h1, l1;
          split2(x0.x * rv00, h0, l0);
          split2(x0.y * rv01, h1, l1);
          *(__nv_bfloat162*)(g_Ahi + r0 * AW + tb * 128 + col) = __nv_bfloat162(h0, h1);
          *(__nv_bfloat162*)(g_Alo + r0 * AW + tb * 128 + col) = __nv_bfloat162(l0, l1);
          split2(x1.x * rv10, h0, l0);
          split2(x1.y * rv11, h1, l1);
          *(__nv_bfloat162*)(g_Ahi + r1 * AW + tb * 128 + col) = __nv_bfloat162(h0, h1);
          *(__nv_bfloat162*)(g_Alo + r1 * AW + tb * 128 + col) = __nv_bfloat162(l0, l1);
        }
      }
    }
    return;
  }

  // ---- normal epilogue ----
  const float* bp = (cfg.biasc >= 0) ? bias + cfg.biasc : nullptr;
#pragma unroll
  for (int m = 0; m < 2; ++m) {
#pragma unroll
    for (int n = 0; n < 8; ++n) {
      const int col = wc * 64 + n * 8 + tg * 2;
      float b0v = 0.f, b1v = 0.f;
      if (bp) { b0v = bp[col]; b1v = bp[col + 1]; }
      const size_t row = e0 + wr * 32 + m * 16 + gq;
      float* d0 = outp + row * (size_t)ostride + cfg.col0 + col;
      float* d1 = d0 + 8 * (size_t)ostride;
      *(float2*)d0 = make_float2(acc[m][n][0] + b0v, acc[m][n][1] + b1v);
      *(float2*)d1 = make_float2(acc[m][n][2] + b0v, acc[m][n][3] + b1v);
    }
  }
}

// ============================================================================
// Radial MLP layers 1+2 (fused LN+SiLU), SIMT; writes split-bf16 h2.
// ============================================================================
__device__ __forceinline__ void zero_acc8(float acc[4][8]) {
#pragma unroll
  for (int ee = 0; ee < 4; ++ee)
#pragma unroll
    for (int jj = 0; jj < 8; ++jj) acc[ee][jj] = 0.f;
}

__device__ __forceinline__ void rad_gemm128(const float* __restrict__ AT,
                                            const float* __restrict__ Wg,
                                            float* __restrict__ WS,
                                            float acc[4][8],
                                            int ty, int tx, int t)
{
  const int jL = t >> 1;
  const int kk0 = (t & 1) * 16;
  const float* wrow = Wg + jL * 128 + kk0;
#pragma unroll 1
  for (int kcu = 0; kcu < 4; ++kcu) {
#pragma unroll
    for (int u = 0; u < 4; ++u) {
      float4 v = *(const float4*)(wrow + kcu * 32 + u * 4);
      const int kk = kk0 + u * 4;
      WS[(kk + 0) * 132 + jL] = v.x;
      WS[(kk + 1) * 132 + jL] = v.y;
      WS[(kk + 2) * 132 + jL] = v.z;
      WS[(kk + 3) * 132 + jL] = v.w;
    }
    __syncthreads();
#pragma unroll
    for (int kk = 0; kk < 32; ++kk) {
      float4 a  = *(const float4*)(AT + (kcu * 32 + kk) * 68 + ty * 4);
      float4 b0 = *(const float4*)(WS + kk * 132 + tx * 8);
      float4 b1 = *(const float4*)(WS + kk * 132 + tx * 8 + 4);
      float av[4] = {a.x, a.y, a.z, a.w};
      float bv[8] = {b0.x, b0.y, b0.z, b0.w, b1.x, b1.y, b1.z, b1.w};
#pragma unroll
      for (int ee = 0; ee < 4; ++ee)
#pragma unroll
        for (int jj = 0; jj < 8; ++jj)
          acc[ee][jj] = fmaf(av[ee], bv[jj], acc[ee][jj]);
    }
    __syncthreads();
  }
}

__device__ __forceinline__ void store_bias_T(float* __restrict__ OT,
                                             const float acc[4][8],
                                             const float* __restrict__ bias,
                                             int ty, int tx)
{
  float4 q0 = *(const float4*)(bias + tx * 8);
  float4 q1 = *(const float4*)(bias + tx * 8 + 4);
  float bb[8] = {q0.x, q0.y, q0.z, q0.w, q1.x, q1.y, q1.z, q1.w};
#pragma unroll
  for (int jj = 0; jj < 8; ++jj) {
    const int j = tx * 8 + jj;
#pragma unroll
    for (int ee = 0; ee < 4; ++ee)
      OT[j * 68 + ty * 4 + ee] = acc[ee][jj] + bb[jj];
  }
}

__device__ __forceinline__ void ln_silu(float* __restrict__ HT,
                                        const float* __restrict__ g,
                                        const float* __restrict__ be, int t)
{
  const int e = t >> 2, q = t & 3;
  float vv[32];
  float s = 0.f, s2 = 0.f;
#pragma unroll
  for (int u = 0; u < 32; ++u) {
    float v = HT[(q * 32 + u) * 68 + e];
    vv[u] = v; s += v; s2 += v * v;
  }
  s  += __shfl_xor_sync(0xffffffffu, s, 1);
  s2 += __shfl_xor_sync(0xffffffffu, s2, 1);
  s  += __shfl_xor_sync(0xffffffffu, s, 2);
  s2 += __shfl_xor_sync(0xffffffffu, s2, 2);
  const float mu  = s * (1.0f / 128.0f);
  const float var = fmaf(-mu, mu, s2 * (1.0f / 128.0f));
  const float rin = rsqrtf(var + 1e-5f);
#pragma unroll
  for (int u = 0; u < 32; ++u) {
    const int j = q * 32 + u;
    float v = (vv[u] - mu) * rin * g[j] + be[j];
    v = v / (1.0f + expf(-v));
    HT[j * 68 + e] = v;
  }
}

__global__ __launch_bounds__(256)
void radial12_kernel(const float* __restrict__ xe,
                     const float* __restrict__ w1, const float* __restrict__ b1,
                     const float* __restrict__ g1, const float* __restrict__ be1,
                     const float* __restrict__ w2, const float* __restrict__ b2,
                     const float* __restrict__ g2, const float* __restrict__ be2)
{
  extern __shared__ float smx[];
  float* HA = smx;
  float* HB = smx + 128 * 68;
  float* WS = smx + 2 * 128 * 68;
  const int t = threadIdx.x;
  const int ty = t >> 4, tx = t & 15;
  const size_t e0 = (size_t)blockIdx.x * 64;

  {
    const int e = t >> 2, q = t & 3;
    const float* src = xe + (e0 + e) * 128 + q * 32;
#pragma unroll
    for (int u = 0; u < 8; ++u) {
      float4 v = *(const float4*)(src + u * 4);
      const int k = q * 32 + u * 4;
      HA[(k + 0) * 68 + e] = v.x;
      HA[(k + 1) * 68 + e] = v.y;
      HA[(k + 2) * 68 + e] = v.z;
      HA[(k + 3) * 68 + e] = v.w;
    }
  }
  __syncthreads();

  float acc[4][8];
  zero_acc8(acc);
  rad_gemm128(HA, w1, WS, acc, ty, tx, t);
  store_bias_T(HB, acc, b1, ty, tx);
  __syncthreads();
  ln_silu(HB, g1, be1, t);
  __syncthreads();

  zero_acc8(acc);
  rad_gemm128(HB, w2, WS, acc, ty, tx, t);
  store_bias_T(HA, acc, b2, ty, tx);
  __syncthreads();
  ln_silu(HA, g2, be2, t);

  // write split h2 (same thread wrote these elements in ln_silu -> no sync)
  {
    const int e = t >> 2, q = t & 3;
    __nv_bfloat16* dh = g_h2hi + (e0 + e) * 128 + q * 32;
    __nv_bfloat16* dl = g_h2lo + (e0 + e) * 128 + q * 32;
#pragma unroll
    for (int u = 0; u < 32; u += 2) {
      float v0 = HA[(q * 32 + u) * 68 + e];
      float v1 = HA[(q * 32 + u + 1) * 68 + e];
      __nv_bfloat16 h0, l0, h1, l1;
      split2(v0, h0, l0);
      split2(v1, h1, l1);
      *(__nv_bfloat162*)(dh + u) = __nv_bfloat162(h0, h1);
      *(__nv_bfloat162*)(dl + u) = __nv_bfloat162(l0, l1);
    }
  }
}

// ============================================================================
// single fused weight-split kernel (all 4 segments)
// ============================================================================
__global__ void convsplit_all(const float* __restrict__ fc0w,
                              const float* __restrict__ fc1w,
                              const float* __restrict__ fc2w,
                              const float* __restrict__ rw3)
{
  int i = blockIdx.x * 256 + threadIdx.x;
  if (i >= W_TOT) return;
  float v;
  if (i < W_FC1)      v = fc0w[i];
  else if (i < W_FC2) v = fc1w[i - W_FC1];
  else if (i < W_W3)  v = fc2w[i - W_FC2];
  else                v = rw3[i - W_W3];
  __nv_bfloat16 h, l;
  split2(v, h, l);
  g_Whi[i] = h;
  g_Wlo[i] = l;
}

// ---------------------------------------------------------------------------
extern "C" void kernel_launch(void* const* d_in, const int* in_sizes, int n_in,
                              void* d_out, int out_size)
{
  const float* x    = (const float*)d_in[0];
  const float* xe   = (const float*)d_in[1];
  const float* fc0w = (const float*)d_in[2];
  const float* fc0b = (const float*)d_in[3];
  const float* fc1w = (const float*)d_in[4];
  const float* fc2w = (const float*)d_in[5];
  const float* rw1  = (const float*)d_in[6];
  const float* rb1  = (const float*)d_in[7];
  const float* rg1  = (const float*)d_in[8];
  const float* rbe1 = (const float*)d_in[9];
  const float* rw2  = (const float*)d_in[10];
  const float* rb2  = (const float*)d_in[11];
  const float* rg2  = (const float*)d_in[12];
  const float* rbe2 = (const float*)d_in[13];
  const float* rw3  = (const float*)d_in[14];
  const float* rb3  = (const float*)d_in[15];
  float* out = (float*)d_out;

  const int N = in_sizes[1] / CH;
  const int nb64  = N / 64;
  const int nb128 = N / 128;

  // launch 1: all weight conversions
  convsplit_all<<<(W_TOT + 255) / 256, 256>>>(fc0w, fc1w, fc2w, rw3);

  // launch 2: radial layers 1+2 (SIMT, fused LN+SiLU) -> split h2
  const int smem_r = (2 * 128 * 68 + 32 * 132) * 4;
  cudaFuncSetAttribute(radial12_kernel,
                       cudaFuncAttributeMaxDynamicSharedMemorySize, smem_r);
  radial12_kernel<<<nb64, 256, smem_r>>>(xe, rw1, rb1, rg1, rbe1,
                                         rw2, rb2, rg2, rbe2);

  cudaFuncSetAttribute(mma_gemm,
                       cudaFuncAttributeMaxDynamicSharedMemorySize, SMEM_G);

  // launch 3: radial layer 3 GEMM + fused FiLM/gather/split -> g_Ahi/g_Alo
  mma_gemm<<<dim3(12, nb128), 256, SMEM_G>>>(1, rb3, x, nullptr, 0, 19);

  // launch 4: all 19 SO2 output blocks in one launch
  mma_gemm<<<dim3(19, nb128), 256, SMEM_G>>>(0, fc0b, nullptr, out, KC * CH, 0);
}